// round 9
// baseline (speedup 1.0000x reference)
#include <cuda_runtime.h>
#include <cstdint>

#define BATCH 16
#define H 1024
#define W 1024
#define PLANE (H * W)

#define TX 128
#define TY 16
#define ST_W 136        // x domain: ox0-4 .. ox0+131 (16B aligned base)
#define ST_H 20         // y domain: oy0-2 .. oy0+17
#define SM_H 18         // T_mid y domain: oy0-1 .. oy0+16 (same x domain)
#define NCH 34          // float4 chunks per row

#define NRED 296
#define RED_STRIDE (NRED * 512)

#define DXF ((float)(1.0 / 126.0))

__device__ float g_partial[NRED];

__device__ __forceinline__ void cpa16(uint32_t dst, const float* src) {
    asm volatile("cp.async.cg.shared.global [%0], [%1], 16;\n"
                 :: "r"(dst), "l"(src));
}
__device__ __forceinline__ void cpa_commit_wait() {
    asm volatile("cp.async.commit_group;\n");
    asm volatile("cp.async.wait_group 0;\n");
}

// ---------------------------------------------------------------------------
// Stage A: per-block max |u|,|v| partials. Unroll-4 independent accumulators.
// ---------------------------------------------------------------------------
__global__ __launch_bounds__(512) void k_reduce(const float* __restrict__ in) {
    const int total_vec = BATCH * 2 * PLANE / 4;  // 8388608 float4
    const float4* in4 = (const float4*)in;

    float m0 = 0.f, m1 = 0.f, m2 = 0.f, m3 = 0.f;
    int i = blockIdx.x * 512 + threadIdx.x;

    #define RED_IDX(j) ((j) + ((j) & ~((1 << 19) - 1)))
    for (; i + 3 * RED_STRIDE < total_vec; i += 4 * RED_STRIDE) {
        float4 a = in4[RED_IDX(i)];
        float4 b = in4[RED_IDX(i + RED_STRIDE)];
        float4 c = in4[RED_IDX(i + 2 * RED_STRIDE)];
        float4 d = in4[RED_IDX(i + 3 * RED_STRIDE)];
        m0 = fmaxf(m0, fmaxf(fmaxf(fabsf(a.x), fabsf(a.y)), fmaxf(fabsf(a.z), fabsf(a.w))));
        m1 = fmaxf(m1, fmaxf(fmaxf(fabsf(b.x), fabsf(b.y)), fmaxf(fabsf(b.z), fabsf(b.w))));
        m2 = fmaxf(m2, fmaxf(fmaxf(fabsf(c.x), fabsf(c.y)), fmaxf(fabsf(c.z), fabsf(c.w))));
        m3 = fmaxf(m3, fmaxf(fmaxf(fabsf(d.x), fabsf(d.y)), fmaxf(fabsf(d.z), fabsf(d.w))));
    }
    for (; i < total_vec; i += RED_STRIDE) {
        float4 a = in4[RED_IDX(i)];
        m0 = fmaxf(m0, fmaxf(fmaxf(fabsf(a.x), fabsf(a.y)), fmaxf(fabsf(a.z), fabsf(a.w))));
    }
    float m = fmaxf(fmaxf(m0, m1), fmaxf(m2, m3));

    #pragma unroll
    for (int o = 16; o > 0; o >>= 1)
        m = fmaxf(m, __shfl_xor_sync(0xffffffffu, m, o));
    __shared__ float sm[16];
    int lane = threadIdx.x & 31, w = threadIdx.x >> 5;
    if (lane == 0) sm[w] = m;
    __syncthreads();
    if (w == 0) {
        m = (lane < 16) ? sm[lane] : 0.0f;
        #pragma unroll
        for (int o = 8; o > 0; o >>= 1)
            m = fmaxf(m, __shfl_xor_sync(0xffffffffu, m, o));
        if (lane == 0) g_partial[blockIdx.x] = m;
    }
}

// ---------------------------------------------------------------------------
// Stage B: fused advect + laplacian, everything vectorized by 4.
//   - only T goes through smem (the only operand with reuse)
//   - u, v consumed directly as aligned LDG.128 in stage 2
//   - R prefetched as one LDG.128 per thread; output one STG.128 per thread
// T_mid tile shares the x domain of sT (base ox0-4): its 3 left / 3 right
// padding columns are computed but never read (keeps all LDG.128 aligned).
// ---------------------------------------------------------------------------
__global__ __launch_bounds__(512, 3) void k_fused(const float* __restrict__ in,
                                                  float* __restrict__ out,
                                                  int out_size) {
    __shared__ __align__(16) float sT[ST_H][ST_W];
    __shared__ __align__(16) float sM[SM_H][ST_W];
    __shared__ float s_dt;

    const int bx = blockIdx.x, by = blockIdx.y, b = blockIdx.z;
    const int ox0 = bx * TX, oy0 = by * TY;
    const int gy0 = oy0 - 2;
    const int xbase = ox0 - 4;
    const int tid = threadIdx.x;
    const bool interior = (bx > 0) & (bx < W / TX - 1) &
                          (by > 0) & (by < H / TY - 1);

    const float* base = in + (size_t)b * 4 * PLANE;
    const float* U = base;
    const float* V = base + PLANE;
    const float* T = base + 2 * PLANE;
    const float* R = base + 3 * PLANE;

    // Stage-3 ownership: one row x 4 cols per thread (2048 = 512*4 exactly).
    const int r3 = tid >> 5;            // 0..15
    const int x0 = (tid & 31) << 2;     // 0..124

    // R prefetch (zero reuse -> straight to registers, issued first)
    float4 R4 = __ldg((const float4*)(R + (size_t)(oy0 + r3) * W + ox0 + x0));

    // dt prologue on warp 0 (overlaps staging by other warps)
    if (tid < 32) {
        float m = 0.0f;
        for (int i = tid; i < NRED; i += 32) m = fmaxf(m, g_partial[i]);
        #pragma unroll
        for (int o = 16; o > 0; o >>= 1)
            m = fmaxf(m, __shfl_xor_sync(0xffffffffu, m, o));
        if (tid == 0) {
            float dt_a = 0.5f * 0.1f * DXF / m;
            float dx2 = DXF * DXF;
            float dt_d = 0.5f * (dx2 * dx2) / (dx2 + dx2);
            s_dt = fminf(dt_a, dt_d);
        }
    }

    // ---- stage 1: T_prev -> sT ----
    if (interior) {
        for (int l = tid; l < ST_H * NCH; l += 512) {
            int ro = l / NCH, c = l - ro * NCH;
            cpa16((uint32_t)__cvta_generic_to_shared(&sT[ro][c * 4]),
                  T + (size_t)(gy0 + ro) * W + xbase + c * 4);
        }
        cpa_commit_wait();
    } else {
        for (int l = tid; l < ST_H * ST_W; l += 512) {
            int ro = l / ST_W, sx = l - ro * ST_W;
            int py = min(max(gy0 + ro, 0), H - 1);
            int px = min(max(xbase + sx, 0), W - 1);
            sT[ro][sx] = __ldg(T + (size_t)py * W + px);
        }
    }
    __syncthreads();

    const float dt = s_dt;
    const float rdx = 1.0f / DXF;

    // ---- stage 2: advect -> sM, 4 outputs per task ----
    if (interior) {
        for (int l = tid; l < SM_H * NCH; l += 512) {
            int my = l / NCH, c = l - my * NCH;
            int mx = c << 2;
            const float* rC = &sT[my + 1][0];

            float4 cc = *(const float4*)(rC + mx);
            float lm = rC[max(mx - 1, 0)];           // padding slot if clamped
            float rp = rC[min(mx + 4, ST_W - 1)];    // padding slot if clamped
            float4 tp = *(const float4*)(&sT[my][mx]);
            float4 bt = *(const float4*)(&sT[my + 2][mx]);

            size_t goff = (size_t)(oy0 - 1 + my) * W + xbase + mx;
            float4 u4 = __ldg((const float4*)(U + goff));
            float4 v4 = __ldg((const float4*)(V + goff));

            float cA[4] = {cc.x, cc.y, cc.z, cc.w};
            float lA[4] = {lm, cc.x, cc.y, cc.z};
            float rA[4] = {cc.y, cc.z, cc.w, rp};
            float tA[4] = {tp.x, tp.y, tp.z, tp.w};
            float bA[4] = {bt.x, bt.y, bt.z, bt.w};
            float uA[4] = {u4.x, u4.y, u4.z, u4.w};
            float vA[4] = {v4.x, v4.y, v4.z, v4.w};
            float res[4];
            #pragma unroll
            for (int e = 0; e < 4; ++e) {
                float gx = (uA[e] > 0.0f) ? (cA[e] - lA[e]) * rdx
                         : ((uA[e] < 0.0f) ? (rA[e] - cA[e]) * rdx : 0.0f);
                float gy = (vA[e] > 0.0f) ? (cA[e] - tA[e]) * rdx
                         : ((vA[e] < 0.0f) ? (bA[e] - cA[e]) * rdx : 0.0f);
                res[e] = cA[e] + dt * (-uA[e] * gx - vA[e] * gy);
            }
            *(float4*)&sM[my][mx] = make_float4(res[0], res[1], res[2], res[3]);
        }
    } else {
        // Scalar clamped path. Slot-index clamps only ever trigger in padding
        // columns (mx<3 or mx>132) which stage 3 never reads.
        for (int l = tid; l < SM_H * ST_W; l += 512) {
            int my = l / ST_W, mx = l - my * ST_W;
            int py = min(max(oy0 - 1 + my, 0), H - 1);
            int px = min(max(xbase + mx, 0), W - 1);
            int sy = py - gy0;
            int sx = px - xbase;
            int sxm = max(sx - 1, 0), sxp = min(sx + 1, ST_W - 1);
            int sym = max(sy - 1, 0), syp = min(sy + 1, ST_H - 1);
            float c   = sT[sy][sx];
            float lft = sT[sy][sxm];
            float rgt = sT[sy][sxp];
            float top = sT[sym][sx];
            float bot = sT[syp][sx];
            size_t gidx = (size_t)py * W + px;
            float u = __ldg(U + gidx);
            float v = __ldg(V + gidx);
            float gx = (u > 0.0f) ? (c - lft) * rdx
                     : ((u < 0.0f) ? (rgt - c) * rdx : 0.0f);
            float gy = (v > 0.0f) ? (c - top) * rdx
                     : ((v < 0.0f) ? (bot - c) * rdx : 0.0f);
            sM[my][mx] = c + dt * (-u * gx - v * gy);
        }
    }
    __syncthreads();

    // ---- stage 3: separable laplacian, 1 row x 4 cols per thread ----
    {
        // output (oy0+r3, ox0+x0..x0+3); T_mid global px -> sM col px-xbase
        // needed cols: x0+3 .. x0+8 ; rows my = r3, r3+1, r3+2
        float hb[3][4];
        float4 ctr;
        #pragma unroll
        for (int rr = 0; rr < 3; ++rr) {
            const float* row = &sM[r3 + rr][0];
            float a = row[x0 + 3];
            float4 mid = *(const float4*)(row + x0 + 4);
            float z = row[x0 + 8];
            hb[rr][0] = a + 2.0f * mid.x + mid.y;
            hb[rr][1] = mid.x + 2.0f * mid.y + mid.z;
            hb[rr][2] = mid.y + 2.0f * mid.z + mid.w;
            hb[rr][3] = mid.z + 2.0f * mid.w + z;
            if (rr == 1) ctr = mid;
        }
        const float lapc = 0.25f * rdx * rdx;
        const float c4 = 4.0f * rdx * rdx;
        float4 o;
        o.x = ctr.x + dt * (lapc * (hb[0][0] + 2.0f * hb[1][0] + hb[2][0]) - c4 * ctr.x + R4.x);
        o.y = ctr.y + dt * (lapc * (hb[0][1] + 2.0f * hb[1][1] + hb[2][1]) - c4 * ctr.y + R4.y);
        o.z = ctr.z + dt * (lapc * (hb[0][2] + 2.0f * hb[1][2] + hb[2][2]) - c4 * ctr.z + R4.z);
        o.w = ctr.w + dt * (lapc * (hb[0][3] + 2.0f * hb[1][3] + hb[2][3]) - c4 * ctr.w + R4.w);
        *(float4*)(out + (size_t)b * PLANE + (size_t)(oy0 + r3) * W + ox0 + x0) = o;
    }

    // scalar dt — second output element
    if (bx == 0 && by == 0 && b == 0 && tid == 0 && out_size > BATCH * PLANE)
        out[BATCH * PLANE] = dt;
}

extern "C" void kernel_launch(void* const* d_in, const int* in_sizes, int n_in,
                              void* d_out, int out_size) {
    const float* in = (const float*)d_in[0];
    float* out = (float*)d_out;
    (void)in_sizes; (void)n_in;

    k_reduce<<<NRED, 512>>>(in);

    dim3 grd(W / TX, H / TY, BATCH);
    k_fused<<<grd, 512>>>(in, out, out_size);
}